// round 7
// baseline (speedup 1.0000x reference)
#include <cuda_runtime.h>

#define N      512
#define D      2048
#define LDIM   128
#define PARTS  8
#define SPLITS 16
#define KZ     (D / SPLITS)   // 128
#define BM     64
#define BN     64
#define BK     16
#define NTILES 36             // symmetric tiles (mt<=nt) of 8x8 tile grid
#define MARGIN 0.3f

// ---------------- device scratch (static allocation only) ----------------
__device__ float g_sq[N];
__device__ float g_gram[SPLITS][N * N];   // 16 MB: split-K partial Gram matrices
__device__ float g_gl[N];
__device__ float g_ll[N];

// symmetric tile list: all (mt, nt) with mt <= nt, 8x8 tile grid
__constant__ unsigned char c_mt[NTILES] = {
    0,0,0,0,0,0,0,0, 1,1,1,1,1,1,1, 2,2,2,2,2,2, 3,3,3,3,3, 4,4,4,4, 5,5,5, 6,6, 7};
__constant__ unsigned char c_nt[NTILES] = {
    0,1,2,3,4,5,6,7, 1,2,3,4,5,6,7, 2,3,4,5,6,7, 3,4,5,6,7, 4,5,6,7, 5,6,7, 6,7, 7};

// packed f32x2 FMA: d.lo += a.lo*b.lo ; d.hi += a.hi*b.hi
__device__ __forceinline__ void fma2(unsigned long long& d,
                                     unsigned long long a,
                                     unsigned long long b) {
    asm("fma.rn.f32x2 %0, %1, %2, %0;" : "+l"(d) : "l"(a), "l"(b));
}
__device__ __forceinline__ unsigned long long pack2(float x, float y) {
    unsigned long long u;
    asm("mov.b64 %0, {%1,%2};" : "=l"(u) : "f"(x), "f"(y));
    return u;
}

// ---------------- kernel 1: symmetric split-K Gram + row norms ----------------
// grid (NTILES+1, SPLITS) = (37, 16) = 592 blocks = 148 SMs x 4 co-resident.
// 2-stage smem pipeline: LDG for kc+1 issued before compute of kc, single
// __syncthreads per kc.
__global__ void __launch_bounds__(128, 4)
gram_norms_kernel(const float* __restrict__ X) {
    const int split = blockIdx.y;

    if (blockIdx.x == NTILES) {
        // norms for rows split*32 .. split*32+31 (4 threads per row)
        const int row = split * 32 + (threadIdx.x >> 2);
        const int qu  = threadIdx.x & 3;
        const float4* x4 = reinterpret_cast<const float4*>(X + (size_t)row * D)
                           + qu * (D / 16);
        float s = 0.0f;
#pragma unroll 8
        for (int k = 0; k < D / 16; k++) {
            float4 v = x4[k];
            s += v.x * v.x + v.y * v.y + v.z * v.z + v.w * v.w;
        }
        s += __shfl_xor_sync(0xffffffffu, s, 1);
        s += __shfl_xor_sync(0xffffffffu, s, 2);
        if (qu == 0) g_sq[row] = s;
        return;
    }

    __shared__ unsigned long long As[2][BK / 2][BM + 1];  // [stage][8][65]
    __shared__ unsigned long long Bs[2][BK / 2][BN + 1];

    const int tid = threadIdx.x;
    const int tx  = tid & 7;    // 0..7  (col group)
    const int ty  = tid >> 3;   // 0..15 (row group)
    const int m0  = (int)c_mt[blockIdx.x] * BM;
    const int n0  = (int)c_nt[blockIdx.x] * BN;
    const int kz  = split * KZ;

    // each thread stages 2 float4 for A and 2 for B per kc
    const int r0l = tid >> 2;          // row for load slot 0
    const int c4  = tid & 3;           // float4 index within 16-k row chunk
    const float* Ap0 = X + (size_t)(m0 + r0l)      * D + kz + c4 * 4;
    const float* Ap1 = X + (size_t)(m0 + r0l + 32) * D + kz + c4 * 4;
    const float* Bp0 = X + (size_t)(n0 + r0l)      * D + kz + c4 * 4;
    const float* Bp1 = X + (size_t)(n0 + r0l + 32) * D + kz + c4 * 4;

    unsigned long long acc[4][8];
#pragma unroll
    for (int r = 0; r < 4; r++)
#pragma unroll
        for (int c = 0; c < 8; c++) acc[r][c] = 0ull;

    // prologue: load kc=0 into stage 0
    float4 va0 = *reinterpret_cast<const float4*>(Ap0);
    float4 va1 = *reinterpret_cast<const float4*>(Ap1);
    float4 vb0 = *reinterpret_cast<const float4*>(Bp0);
    float4 vb1 = *reinterpret_cast<const float4*>(Bp1);
    As[0][c4 * 2][r0l]          = pack2(va0.x, va0.y);
    As[0][c4 * 2 + 1][r0l]      = pack2(va0.z, va0.w);
    As[0][c4 * 2][r0l + 32]     = pack2(va1.x, va1.y);
    As[0][c4 * 2 + 1][r0l + 32] = pack2(va1.z, va1.w);
    Bs[0][c4 * 2][r0l]          = pack2(vb0.x, vb0.y);
    Bs[0][c4 * 2 + 1][r0l]      = pack2(vb0.z, vb0.w);
    Bs[0][c4 * 2][r0l + 32]     = pack2(vb1.x, vb1.y);
    Bs[0][c4 * 2 + 1][r0l + 32] = pack2(vb1.z, vb1.w);
    __syncthreads();

#pragma unroll 1
    for (int kc = 0; kc < KZ / BK; kc++) {
        const int buf = kc & 1;

        // prefetch kc+1 (LDG latency overlapped with compute below)
        if (kc + 1 < KZ / BK) {
            const int off = (kc + 1) * BK;
            va0 = *reinterpret_cast<const float4*>(Ap0 + off);
            va1 = *reinterpret_cast<const float4*>(Ap1 + off);
            vb0 = *reinterpret_cast<const float4*>(Bp0 + off);
            vb1 = *reinterpret_cast<const float4*>(Bp1 + off);
        }

#pragma unroll
        for (int k2 = 0; k2 < BK / 2; k2++) {
            unsigned long long a[4], b[8];
#pragma unroll
            for (int r = 0; r < 4; r++) a[r] = As[buf][k2][ty + 16 * r];
#pragma unroll
            for (int c = 0; c < 8; c++) b[c] = Bs[buf][k2][tx + 8 * c];
#pragma unroll
            for (int r = 0; r < 4; r++)
#pragma unroll
                for (int c = 0; c < 8; c++) fma2(acc[r][c], a[r], b[c]);
        }

        if (kc + 1 < KZ / BK) {
            const int nb = buf ^ 1;
            As[nb][c4 * 2][r0l]          = pack2(va0.x, va0.y);
            As[nb][c4 * 2 + 1][r0l]      = pack2(va0.z, va0.w);
            As[nb][c4 * 2][r0l + 32]     = pack2(va1.x, va1.y);
            As[nb][c4 * 2 + 1][r0l + 32] = pack2(va1.z, va1.w);
            Bs[nb][c4 * 2][r0l]          = pack2(vb0.x, vb0.y);
            Bs[nb][c4 * 2 + 1][r0l]      = pack2(vb0.z, vb0.w);
            Bs[nb][c4 * 2][r0l + 32]     = pack2(vb1.x, vb1.y);
            Bs[nb][c4 * 2 + 1][r0l + 32] = pack2(vb1.z, vb1.w);
            __syncthreads();
        }
    }

    // write tile + mirrored tile (values bitwise identical: same k-order, a*b==b*a)
    float* out = g_gram[split];
#pragma unroll
    for (int r = 0; r < 4; r++) {
        int m = m0 + ty + 16 * r;
#pragma unroll
        for (int c = 0; c < 8; c++) {
            int n = n0 + tx + 8 * c;
            float lo = __uint_as_float((unsigned)(acc[r][c] & 0xffffffffull));
            float hi = __uint_as_float((unsigned)(acc[r][c] >> 32));
            float v = lo + hi;
            out[(size_t)m * N + n] = v;
            out[(size_t)n * N + m] = v;
        }
    }
}

// ---------------- kernel 2: fused hard mining + local DTW loss ----------------
// One block per row i. Each thread owns 4 consecutive j (float4 loads).
__global__ void __launch_bounds__(128)
mine_local_kernel(const void* __restrict__ targets_raw,
                  const float* __restrict__ LF) {
    const int i = blockIdx.x;
    const int t = threadIdx.x;

    // dtype detection: targets = j//4 -> word[5] is nonzero for int32 layout,
    // 0 for int64 layout (high word of entry 2). Reads stay in bounds.
    const int* ip = reinterpret_cast<const int*>(targets_raw);
    const int stride = (ip[5] == 0) ? 2 : 1;

    const int   ti  = ip[(size_t)i * stride];
    const float sqi = g_sq[i];

    const int j0 = t * 4;
    float4 g = make_float4(0.f, 0.f, 0.f, 0.f);
#pragma unroll
    for (int s = 0; s < SPLITS; s++) {
        float4 v = *reinterpret_cast<const float4*>(&g_gram[s][(size_t)i * N + j0]);
        g.x += v.x; g.y += v.y; g.z += v.z; g.w += v.w;
    }

    float apv = -3.0e38f; int apj = N;
    float anv =  3.0e38f; int anj = N;
    float gv[4] = {g.x, g.y, g.z, g.w};
#pragma unroll
    for (int u = 0; u < 4; u++) {
        int j = j0 + u;
        float d = sqrtf(fmaxf(sqi + g_sq[j] - 2.0f * gv[u], 1e-12f));
        if (ip[(size_t)j * stride] == ti) {
            if (d > apv) { apv = d; apj = j; }   // strict > keeps first index
        } else {
            if (d < anv) { anv = d; anj = j; }
        }
    }
#pragma unroll
    for (int o = 16; o > 0; o >>= 1) {
        float v = __shfl_down_sync(0xffffffffu, apv, o);
        int   j = __shfl_down_sync(0xffffffffu, apj, o);
        if (v > apv || (v == apv && j < apj)) { apv = v; apj = j; }
        v = __shfl_down_sync(0xffffffffu, anv, o);
        j = __shfl_down_sync(0xffffffffu, anj, o);
        if (v < anv || (v == anv && j < anj)) { anv = v; anj = j; }
    }
    __shared__ float sapv[4], sanv[4];
    __shared__ int   sapj[4], sanj[4];
    __shared__ int   s_pi, s_ni;
    if ((t & 31) == 0) {
        int w = t >> 5;
        sapv[w] = apv; sapj[w] = apj;
        sanv[w] = anv; sanj[w] = anj;
    }
    __syncthreads();
    if (t == 0) {
        for (int w = 1; w < 4; w++) {
            if (sapv[w] > apv || (sapv[w] == apv && sapj[w] < apj)) { apv = sapv[w]; apj = sapj[w]; }
            if (sanv[w] < anv || (sanv[w] == anv && sanj[w] < anj)) { anv = sanv[w]; anj = sanj[w]; }
        }
        s_pi = apj;
        s_ni = anj;
        g_gl[i] = fmaxf(0.0f, MARGIN + apv - anv);
    }
    __syncthreads();

    // ---- local aligned (DTW) loss on parts of (i, hardest-pos, hardest-neg) ----
    __shared__ float sa[PARTS][LDIM + 4];
    __shared__ float sb[PARTS][LDIM + 4];
    __shared__ float sc[PARTS][LDIM + 4];
    __shared__ float dA[PARTS][PARTS];
    __shared__ float dB[PARTS][PARTS];
    __shared__ float res[2];

    const float* A = LF + (size_t)i    * (LDIM * PARTS);
    const float* B = LF + (size_t)s_pi * (LDIM * PARTS);
    const float* C = LF + (size_t)s_ni * (LDIM * PARTS);

    // gmem layout: [i][d][p] -> part-major in smem: sa[p][d]
    for (int idx = t; idx < LDIM * PARTS; idx += 128) {
        int d = idx >> 3, p = idx & 7;
        sa[p][d] = A[idx];
        sb[p][d] = B[idx];
        sc[p][d] = C[idx];
    }
    __syncthreads();

    if (t < 64) {
        const int p = t >> 3, q = t & 7;
        float s1 = 0.0f, s2 = 0.0f;
#pragma unroll 8
        for (int d = 0; d < LDIM; d++) {
            float av = sa[p][d];
            float x = av - sb[q][d]; s1 += x * x;
            float y = av - sc[q][d]; s2 += y * y;
        }
        dA[p][q] = tanhf(0.5f * sqrtf(fmaxf(s1, 1e-12f)));
        dB[p][q] = tanhf(0.5f * sqrtf(fmaxf(s2, 1e-12f)));
    }
    __syncthreads();

    if (t < 2) {
        float (*dm)[PARTS] = (t == 0) ? dA : dB;
        float prev[PARTS];
        prev[0] = 0.0f;
#pragma unroll
        for (int j = 1; j < PARTS; j++) prev[j] = 1e9f;
#pragma unroll
        for (int r = 0; r < PARTS; r++) {
            float left = 1e9f;
#pragma unroll
            for (int j = 0; j < PARTS; j++) {
                float cur = dm[r][j] + fminf(prev[j], left);
                prev[j] = cur;
                left = cur;
            }
        }
        res[t] = prev[PARTS - 1];
    }
    __syncthreads();
    if (t == 0)
        g_ll[i] = fmaxf(0.0f, MARGIN + res[0] - res[1]);
}

// ---------------- kernel 3: deterministic final reduction ----------------
__global__ void reduce_kernel(float* __restrict__ out) {
    const int t = threadIdx.x;   // 512 threads
    float a = g_gl[t];
    float b = g_ll[t];
#pragma unroll
    for (int o = 16; o > 0; o >>= 1) {
        a += __shfl_down_sync(0xffffffffu, a, o);
        b += __shfl_down_sync(0xffffffffu, b, o);
    }
    __shared__ float wa[16], wb[16];
    if ((t & 31) == 0) { wa[t >> 5] = a; wb[t >> 5] = b; }
    __syncthreads();
    if (t < 16) {
        a = wa[t]; b = wb[t];
#pragma unroll
        for (int o = 8; o > 0; o >>= 1) {
            a += __shfl_down_sync(0xffffu, a, o);
            b += __shfl_down_sync(0xffffu, b, o);
        }
        if (t == 0) {
            out[0] = a * (1.0f / N);
            out[1] = b * (1.0f / N);
        }
    }
}

// ---------------- launch ----------------
extern "C" void kernel_launch(void* const* d_in, const int* in_sizes, int n_in,
                              void* d_out, int out_size) {
    const float* X  = (const float*)d_in[0];
    const void*  TG = d_in[1];
    const float* LF = (const float*)d_in[2];
    float* out = (float*)d_out;

    dim3 gg(NTILES + 1, SPLITS);          // 37 x 16 = 592 blocks = 148 SMs x 4
    gram_norms_kernel<<<gg, 128>>>(X);
    mine_local_kernel<<<N, 128>>>(TG, LF);
    reduce_kernel<<<1, 512>>>(out);
}

// round 9
// speedup vs baseline: 1.7471x; 1.7471x over previous
#include <cuda_runtime.h>
#include <cuda_bf16.h>

#define N       512
#define D       2048
#define LDIM    128
#define PARTS   8
#define SPLITK  4
#define KSPLIT  (D / SPLITK)       // 512
#define KC      32                 // k per pipeline chunk
#define NCH     (KSPLIT / KC)      // 16
#define NTILES  36
#define MARGIN  0.3f

#define SM_STRIDE 80                       // bytes per smem row (32 bf16 + 8 pad)
#define TILE_B    (64 * SM_STRIDE)         // 5120
#define STAGE_B   (4 * TILE_B)             // 20480 (Ah, Al, Bh, Bl)

// ---------------- device scratch (static allocation only) ----------------
__device__ float          g_sq[N];
__device__ __nv_bfloat16  g_xh[N * D];
__device__ __nv_bfloat16  g_xl[N * D];
__device__ float          g_gram[SPLITK][N * N];
__device__ float          g_gl[N];
__device__ float          g_ll[N];

// symmetric tile list: all (mt, nt) with mt <= nt on the 8x8 grid of 64x64 tiles
__constant__ unsigned char c_mt[NTILES] = {
    0,0,0,0,0,0,0,0, 1,1,1,1,1,1,1, 2,2,2,2,2,2, 3,3,3,3,3, 4,4,4,4, 5,5,5, 6,6, 7};
__constant__ unsigned char c_nt[NTILES] = {
    0,1,2,3,4,5,6,7, 1,2,3,4,5,6,7, 2,3,4,5,6,7, 3,4,5,6,7, 4,5,6,7, 5,6,7, 6,7, 7};

// ---------------- helpers ----------------
__device__ __forceinline__ unsigned s2u(const void* p) {
    unsigned a;
    asm("{ .reg .u64 t; cvta.to.shared.u64 t, %1; cvt.u32.u64 %0, t; }"
        : "=r"(a) : "l"(p));
    return a;
}
__device__ __forceinline__ void cpa16(unsigned saddr, const void* gaddr) {
    asm volatile("cp.async.cg.shared.global [%0], [%1], 16;"
                 :: "r"(saddr), "l"(gaddr) : "memory");
}
__device__ __forceinline__ void ldm4(unsigned* f, unsigned saddr) {
    asm volatile("ldmatrix.sync.aligned.m8n8.x4.shared.b16 {%0,%1,%2,%3}, [%4];"
                 : "=r"(f[0]), "=r"(f[1]), "=r"(f[2]), "=r"(f[3]) : "r"(saddr));
}
__device__ __forceinline__ void mma_bf16(float* d, const unsigned* a,
                                         unsigned b0, unsigned b1) {
    asm volatile(
        "mma.sync.aligned.m16n8k16.row.col.f32.bf16.bf16.f32 "
        "{%0,%1,%2,%3}, {%4,%5,%6,%7}, {%8,%9}, {%0,%1,%2,%3};"
        : "+f"(d[0]), "+f"(d[1]), "+f"(d[2]), "+f"(d[3])
        : "r"(a[0]), "r"(a[1]), "r"(a[2]), "r"(a[3]), "r"(b0), "r"(b1));
}

// ---------------- kernel 1: fp32 -> bf16 hi/lo split + row norms ----------------
__global__ void __launch_bounds__(256)
convert_kernel(const float* __restrict__ X) {
    const int row = blockIdx.x;
    const int t   = threadIdx.x;
    const float4* x4 = reinterpret_cast<const float4*>(X + (size_t)row * D);
    __nv_bfloat162* xh2 = reinterpret_cast<__nv_bfloat162*>(g_xh + (size_t)row * D);
    __nv_bfloat162* xl2 = reinterpret_cast<__nv_bfloat162*>(g_xl + (size_t)row * D);

    float s = 0.0f;
#pragma unroll
    for (int it = 0; it < 2; it++) {
        int idx = t + 256 * it;          // float4 index, 0..511
        float4 v = x4[idx];
        s += v.x * v.x + v.y * v.y + v.z * v.z + v.w * v.w;
        __nv_bfloat16 hx = __float2bfloat16_rn(v.x);
        __nv_bfloat16 hy = __float2bfloat16_rn(v.y);
        __nv_bfloat16 hz = __float2bfloat16_rn(v.z);
        __nv_bfloat16 hw = __float2bfloat16_rn(v.w);
        __nv_bfloat16 lx = __float2bfloat16_rn(v.x - __bfloat162float(hx));
        __nv_bfloat16 ly = __float2bfloat16_rn(v.y - __bfloat162float(hy));
        __nv_bfloat16 lz = __float2bfloat16_rn(v.z - __bfloat162float(hz));
        __nv_bfloat16 lw = __float2bfloat16_rn(v.w - __bfloat162float(hw));
        xh2[idx * 2]     = __nv_bfloat162(hx, hy);
        xh2[idx * 2 + 1] = __nv_bfloat162(hz, hw);
        xl2[idx * 2]     = __nv_bfloat162(lx, ly);
        xl2[idx * 2 + 1] = __nv_bfloat162(lz, lw);
    }
#pragma unroll
    for (int o = 16; o > 0; o >>= 1) s += __shfl_down_sync(0xffffffffu, s, o);
    __shared__ float ws[8];
    if ((t & 31) == 0) ws[t >> 5] = s;
    __syncthreads();
    if (t < 8) {
        s = ws[t];
#pragma unroll
        for (int o = 4; o > 0; o >>= 1) s += __shfl_down_sync(0xffu, s, o);
        if (t == 0) g_sq[row] = s;
    }
}

// ---------------- kernel 2: Gram via mma.sync bf16, 3-term split ----------------
// grid (36, 4): symmetric 64x64 tiles x split-K. 256 threads = 8 warps (4x2),
// warp tile 16x32. cp.async double-buffered pipeline.
__global__ void __launch_bounds__(256, 1)
gram_mma_kernel() {
    __shared__ __align__(16) char sm[2 * STAGE_B];   // 40 KB
    const unsigned smu = s2u(sm);

    const int tid  = threadIdx.x;
    const int wid  = tid >> 5;
    const int lane = tid & 31;
    const int wr   = wid & 3;           // warp row 0..3 -> m offset wr*16
    const int wc   = wid >> 2;          // warp col 0..1 -> n offset wc*32
    const int m0   = (int)c_mt[blockIdx.x] * 64;
    const int n0   = (int)c_nt[blockIdx.x] * 64;
    const int split = blockIdx.y;
    const int kz   = split * KSPLIT;

    // per-thread cp.async slots: 256 chunks of 16B per tile, 1 per thread
    const int lr  = tid >> 2;           // smem row 0..63
    const int lch = tid & 3;            // 16B chunk within row
    const unsigned dst_off = (unsigned)(lr * SM_STRIDE + lch * 16);
    const size_t   src_off = (size_t)lr * D + lch * 8;
    const __nv_bfloat16* Amh = g_xh + (size_t)m0 * D + src_off;
    const __nv_bfloat16* Aml = g_xl + (size_t)m0 * D + src_off;
    const __nv_bfloat16* Bnh = g_xh + (size_t)n0 * D + src_off;
    const __nv_bfloat16* Bnl = g_xl + (size_t)n0 * D + src_off;

    // ldmatrix per-lane offsets (bytes, within a stage)
    const unsigned aOff = (unsigned)((wr * 16 + (lane & 15)) * SM_STRIDE
                                     + ((lane >> 4) << 4));
    unsigned bOff[2];
#pragma unroll
    for (int p = 0; p < 2; p++)
        bOff[p] = (unsigned)((wc * 32 + p * 16 + ((lane >> 4) & 1) * 8 + (lane & 7))
                             * SM_STRIDE + ((lane >> 3) & 1) * 16);

    float acc[4][4];
#pragma unroll
    for (int nt = 0; nt < 4; nt++)
#pragma unroll
        for (int e = 0; e < 4; e++) acc[nt][e] = 0.0f;

    // prologue: chunks 0 and 1
#pragma unroll
    for (int c = 0; c < 2; c++) {
        const unsigned sb = smu + c * STAGE_B + dst_off;
        const size_t   gk = kz + c * KC;
        cpa16(sb,              Amh + gk);
        cpa16(sb + TILE_B,     Aml + gk);
        cpa16(sb + 2 * TILE_B, Bnh + gk);
        cpa16(sb + 3 * TILE_B, Bnl + gk);
        asm volatile("cp.async.commit_group;" ::: "memory");
    }

#pragma unroll 1
    for (int c = 0; c < NCH; c++) {
        if (c < NCH - 1) asm volatile("cp.async.wait_group 1;" ::: "memory");
        else             asm volatile("cp.async.wait_group 0;" ::: "memory");
        __syncthreads();

        const unsigned st = smu + (c & 1) * STAGE_B;
#pragma unroll
        for (int s16 = 0; s16 < 2; s16++) {
            unsigned ah[4], al[4], bh[8], bl[8];
            const unsigned ka = st + aOff + s16 * 32;
            ldm4(ah, ka);
            ldm4(al, ka + TILE_B);
#pragma unroll
            for (int p = 0; p < 2; p++) {
                const unsigned kb = st + bOff[p] + s16 * 32;
                ldm4(&bh[p * 4], kb + 2 * TILE_B);
                ldm4(&bl[p * 4], kb + 3 * TILE_B);
            }
#pragma unroll
            for (int nt = 0; nt < 4; nt++) {
                const int bi = (nt >> 1) * 4 + (nt & 1) * 2;
                mma_bf16(acc[nt], ah, bh[bi], bh[bi + 1]);  // hh
                mma_bf16(acc[nt], ah, bl[bi], bl[bi + 1]);  // h*l
                mma_bf16(acc[nt], al, bh[bi], bh[bi + 1]);  // l*h
            }
        }
        __syncthreads();

        if (c + 2 < NCH) {
            const unsigned sb = smu + (c & 1) * STAGE_B + dst_off;
            const size_t   gk = kz + (size_t)(c + 2) * KC;
            cpa16(sb,              Amh + gk);
            cpa16(sb + TILE_B,     Aml + gk);
            cpa16(sb + 2 * TILE_B, Bnh + gk);
            cpa16(sb + 3 * TILE_B, Bnl + gk);
            asm volatile("cp.async.commit_group;" ::: "memory");
        }
    }

    // epilogue: direct store + mirrored store for off-diagonal tiles
    float* out = g_gram[split];
    const int rbase = m0 + wr * 16 + (lane >> 2);
    const bool mirror = (m0 != n0);
#pragma unroll
    for (int nt = 0; nt < 4; nt++) {
        const int col = n0 + wc * 32 + nt * 8 + (lane & 3) * 2;
        *reinterpret_cast<float2*>(&out[(size_t)rbase * N + col]) =
            make_float2(acc[nt][0], acc[nt][1]);
        *reinterpret_cast<float2*>(&out[(size_t)(rbase + 8) * N + col]) =
            make_float2(acc[nt][2], acc[nt][3]);
        if (mirror) {
            out[(size_t)col * N + rbase]           = acc[nt][0];
            out[(size_t)(col + 1) * N + rbase]     = acc[nt][1];
            out[(size_t)col * N + rbase + 8]       = acc[nt][2];
            out[(size_t)(col + 1) * N + rbase + 8] = acc[nt][3];
        }
    }
}

// ---------------- kernel 3: fused hard mining + local DTW loss ----------------
__global__ void __launch_bounds__(128)
mine_local_kernel(const void* __restrict__ targets_raw,
                  const float* __restrict__ LF) {
    const int i = blockIdx.x;
    const int t = threadIdx.x;

    // dtype detection: targets = j//4 -> word[5] nonzero for int32 layout, 0 for int64.
    const int* ip = reinterpret_cast<const int*>(targets_raw);
    const int stride = (ip[5] == 0) ? 2 : 1;

    const int   ti  = ip[(size_t)i * stride];
    const float sqi = g_sq[i];

    const int j0 = t * 4;
    float4 g = make_float4(0.f, 0.f, 0.f, 0.f);
#pragma unroll
    for (int s = 0; s < SPLITK; s++) {
        float4 v = *reinterpret_cast<const float4*>(&g_gram[s][(size_t)i * N + j0]);
        g.x += v.x; g.y += v.y; g.z += v.z; g.w += v.w;
    }

    float apv = -3.0e38f; int apj = N;
    float anv =  3.0e38f; int anj = N;
    float gv[4] = {g.x, g.y, g.z, g.w};
#pragma unroll
    for (int u = 0; u < 4; u++) {
        int j = j0 + u;
        float d = sqrtf(fmaxf(sqi + g_sq[j] - 2.0f * gv[u], 1e-12f));
        if (ip[(size_t)j * stride] == ti) {
            if (d > apv) { apv = d; apj = j; }   // strict > keeps first index
        } else {
            if (d < anv) { anv = d; anj = j; }
        }
    }
#pragma unroll
    for (int o = 16; o > 0; o >>= 1) {
        float v = __shfl_down_sync(0xffffffffu, apv, o);
        int   j = __shfl_down_sync(0xffffffffu, apj, o);
        if (v > apv || (v == apv && j < apj)) { apv = v; apj = j; }
        v = __shfl_down_sync(0xffffffffu, anv, o);
        j = __shfl_down_sync(0xffffffffu, anj, o);
        if (v < anv || (v == anv && j < anj)) { anv = v; anj = j; }
    }
    __shared__ float sapv[4], sanv[4];
    __shared__ int   sapj[4], sanj[4];
    __shared__ int   s_pi, s_ni;
    if ((t & 31) == 0) {
        int w = t >> 5;
        sapv[w] = apv; sapj[w] = apj;
        sanv[w] = anv; sanj[w] = anj;
    }
    __syncthreads();
    if (t == 0) {
        for (int w = 1; w < 4; w++) {
            if (sapv[w] > apv || (sapv[w] == apv && sapj[w] < apj)) { apv = sapv[w]; apj = sapj[w]; }
            if (sanv[w] < anv || (sanv[w] == anv && sanj[w] < anj)) { anv = sanv[w]; anj = sanj[w]; }
        }
        s_pi = apj;
        s_ni = anj;
        g_gl[i] = fmaxf(0.0f, MARGIN + apv - anv);
    }
    __syncthreads();

    // ---- local aligned (DTW) loss ----
    __shared__ float sa[PARTS][LDIM + 4];
    __shared__ float sb[PARTS][LDIM + 4];
    __shared__ float sc[PARTS][LDIM + 4];
    __shared__ float dA[PARTS][PARTS];
    __shared__ float dB[PARTS][PARTS];
    __shared__ float res[2];

    const float* A = LF + (size_t)i    * (LDIM * PARTS);
    const float* B = LF + (size_t)s_pi * (LDIM * PARTS);
    const float* C = LF + (size_t)s_ni * (LDIM * PARTS);

    for (int idx = t; idx < LDIM * PARTS; idx += 128) {
        int d = idx >> 3, p = idx & 7;
        sa[p][d] = A[idx];
        sb[p][d] = B[idx];
        sc[p][d] = C[idx];
    }
    __syncthreads();

    if (t < 64) {
        const int p = t >> 3, q = t & 7;
        float s1 = 0.0f, s2 = 0.0f;
#pragma unroll 8
        for (int d = 0; d < LDIM; d++) {
            float av = sa[p][d];
            float x = av - sb[q][d]; s1 += x * x;
            float y = av - sc[q][d]; s2 += y * y;
        }
        dA[p][q] = tanhf(0.5f * sqrtf(fmaxf(s1, 1e-12f)));
        dB[p][q] = tanhf(0.5f * sqrtf(fmaxf(s2, 1e-12f)));
    }
    __syncthreads();

    if (t < 2) {
        float (*dm)[PARTS] = (t == 0) ? dA : dB;
        float prev[PARTS];
        prev[0] = 0.0f;
#pragma unroll
        for (int j = 1; j < PARTS; j++) prev[j] = 1e9f;
#pragma unroll
        for (int r = 0; r < PARTS; r++) {
            float left = 1e9f;
#pragma unroll
            for (int j = 0; j < PARTS; j++) {
                float cur = dm[r][j] + fminf(prev[j], left);
                prev[j] = cur;
                left = cur;
            }
        }
        res[t] = prev[PARTS - 1];
    }
    __syncthreads();
    if (t == 0)
        g_ll[i] = fmaxf(0.0f, MARGIN + res[0] - res[1]);
}

// ---------------- kernel 4: deterministic final reduction ----------------
__global__ void reduce_kernel(float* __restrict__ out) {
    const int t = threadIdx.x;   // 512 threads
    float a = g_gl[t];
    float b = g_ll[t];
#pragma unroll
    for (int o = 16; o > 0; o >>= 1) {
        a += __shfl_down_sync(0xffffffffu, a, o);
        b += __shfl_down_sync(0xffffffffu, b, o);
    }
    __shared__ float wa[16], wb[16];
    if ((t & 31) == 0) { wa[t >> 5] = a; wb[t >> 5] = b; }
    __syncthreads();
    if (t < 16) {
        a = wa[t]; b = wb[t];
#pragma unroll
        for (int o = 8; o > 0; o >>= 1) {
            a += __shfl_down_sync(0xffffu, a, o);
            b += __shfl_down_sync(0xffffu, b, o);
        }
        if (t == 0) {
            out[0] = a * (1.0f / N);
            out[1] = b * (1.0f / N);
        }
    }
}

// ---------------- launch ----------------
extern "C" void kernel_launch(void* const* d_in, const int* in_sizes, int n_in,
                              void* d_out, int out_size) {
    const float* X  = (const float*)d_in[0];
    const void*  TG = d_in[1];
    const float* LF = (const float*)d_in[2];
    float* out = (float*)d_out;

    convert_kernel<<<N, 256>>>(X);
    gram_mma_kernel<<<dim3(NTILES, SPLITK), 256>>>();
    mine_local_kernel<<<N, 128>>>(TG, LF);
    reduce_kernel<<<1, 512>>>(out);
}